// round 16
// baseline (speedup 1.0000x reference)
#include <cuda_runtime.h>

#define Ll 4096
#define Dd 128
#define Cc 32
#define NCH 128
#define BHh 16
#define DVB 16
#define NDVB 8
#define ELEMS (BHh*Ll*Dd)
#define O_ELEMS ((size_t)ELEMS)
#define NCHK (BHh*NCH)
#define NPAIR (NCHK/2)

typedef unsigned long long u64t;
__device__ __forceinline__ u64t pk2s(float a){
    u64t r; asm("mov.b64 %0,{%1,%1};" : "=l"(r) : "f"(a)); return r;
}
__device__ __forceinline__ u64t f2(u64t a, u64t b, u64t c){
    u64t d; asm("fma.rn.f32x2 %0,%1,%2,%3;" : "=l"(d) : "l"(a), "l"(b), "l"(c)); return d;
}
__device__ __forceinline__ float2 up2(u64t p){
    float lo, hi; asm("mov.b64 {%0,%1},%2;" : "=f"(lo), "=f"(hi) : "l"(p));
    return make_float2(lo, hi);
}

// Scratch (__device__ globals)
__device__ float g_qn  [ELEMS];               // q normalized (epilogue)
__device__ float g_u   [ELEMS];               // u = T(v*beta) row-major (scan)
__device__ float g_wT36[NCHK*4608];           // per chunk: w^T [128][36] padded
__device__ float g_kT36[NCHK*4608];           // per chunk: k^T [128][36] padded
__device__ float g_att [NCHK*1024];           // attn_local (epilogue)
__device__ float g_S   [(size_t)NCHK*16384];  // per chunk: S_i col-major [c][d]
__device__ float g_u2  [NCHK*4096];           // per chunk: u' ROW-major [r][c]
__device__ float g_M   [NPAIR*1152];          // per pair: M = w_b k_a^T [32][36]

__device__ __forceinline__ unsigned smem_u32(const void* p){
    unsigned a;
    asm("{ .reg .u64 t; cvta.to.shared.u64 t, %1; cvt.u32.u64 %0, t; }"
        : "=r"(a) : "l"(p));
    return a;
}
__device__ __forceinline__ void mbar_init(unsigned mbar, unsigned cnt){
    asm volatile("mbarrier.init.shared.b64 [%0], %1;" :: "r"(mbar), "r"(cnt) : "memory");
}
__device__ __forceinline__ void mbar_expect_tx(unsigned mbar, unsigned bytes){
    asm volatile("mbarrier.arrive.expect_tx.shared.b64 _, [%0], %1;"
                 :: "r"(mbar), "r"(bytes) : "memory");
}
__device__ __forceinline__ void tma_bulk_g2s(unsigned dst, const void* src,
                                             unsigned bytes, unsigned mbar){
    asm volatile("cp.async.bulk.shared::cta.global.mbarrier::complete_tx::bytes "
                 "[%0], [%1], %2, [%3];"
                 :: "r"(dst), "l"(src), "r"(bytes), "r"(mbar) : "memory");
}
__device__ __forceinline__ void mbar_wait(unsigned mbar, unsigned parity){
    asm volatile("{\n\t.reg .pred P;\n"
                 "WAIT_%=:\n\t"
                 "mbarrier.try_wait.parity.acquire.cta.shared::cta.b64 P, [%0], %1;\n\t"
                 "@!P bra WAIT_%=;\n\t}"
                 :: "r"(mbar), "r"(parity) : "memory");
}

// ----------------------------------------------------------------------------
// Kernel 1: per-chunk preprocessing. grid = 2048, block = 128 (612us winner)
// ----------------------------------------------------------------------------
__global__ __launch_bounds__(128) void prep_kernel(
    const float* __restrict__ q, const float* __restrict__ k,
    const float* __restrict__ v, const float* __restrict__ beta)
{
    extern __shared__ float sm1[];
    float* sqT   = sm1;                // [128][33]
    float* skT   = sqT + 4224;         // [128][33]
    float* svb   = skT + 4224;         // [32][128]
    float* sA    = svb + 4096;         // [32][33]
    float* sbeta = sA  + 1056;         // [32]

    const int tid  = threadIdx.x;
    const int lane = tid & 31;
    const int warp = tid >> 5;
    const int bh = blockIdx.x >> 7;
    const int ci = blockIdx.x & 127;
    const int chk = blockIdx.x;
    const size_t base = ((size_t)bh*Ll + (size_t)ci*Cc)*Dd;

    for (int r = warp*8; r < warp*8 + 8; ++r) {
        float bet = beta[(size_t)bh*Ll + ci*Cc + r];
        const float4 xq = *(const float4*)(q + base + r*Dd + lane*4);
        const float4 xk = *(const float4*)(k + base + r*Dd + lane*4);
        const float4 xv = *(const float4*)(v + base + r*Dd + lane*4);
        float s2q = xq.x*xq.x + xq.y*xq.y + xq.z*xq.z + xq.w*xq.w;
        float s2k = xk.x*xk.x + xk.y*xk.y + xk.z*xk.z + xk.w*xk.w;
        #pragma unroll
        for (int o = 16; o; o >>= 1) {
            s2q += __shfl_xor_sync(0xffffffffu, s2q, o);
            s2k += __shfl_xor_sync(0xffffffffu, s2k, o);
        }
        float iq = rsqrtf(s2q + 1e-6f);
        float ik = rsqrtf(s2k + 1e-6f);
        float4 nq = make_float4(xq.x*iq, xq.y*iq, xq.z*iq, xq.w*iq);
        float4 nk = make_float4(xk.x*ik, xk.y*ik, xk.z*ik, xk.w*ik);
        *(float4*)(g_qn + base + r*Dd + lane*4) = nq;
        const int d0 = lane*4;
        sqT[(d0+0)*33 + r] = nq.x; sqT[(d0+1)*33 + r] = nq.y;
        sqT[(d0+2)*33 + r] = nq.z; sqT[(d0+3)*33 + r] = nq.w;
        skT[(d0+0)*33 + r] = nk.x; skT[(d0+1)*33 + r] = nk.y;
        skT[(d0+2)*33 + r] = nk.z; skT[(d0+3)*33 + r] = nk.w;
        *(float4*)(svb + r*Dd + d0) = make_float4(xv.x*bet, xv.y*bet, xv.z*bet, xv.w*bet);
        if (lane == 0) sbeta[r] = bet;
    }
    __syncthreads();

    // k^T padded [128][36] (TMA target layout)
    {
        const int d = tid;
        #pragma unroll
        for (int r4 = 0; r4 < 32; r4 += 4) {
            *(float4*)&g_kT36[(size_t)chk*4608 + d*36 + r4] = make_float4(
                skT[d*33+r4], skT[d*33+r4+1], skT[d*33+r4+2], skT[d*33+r4+3]);
        }
    }

    // A = -beta_i (k_i.k_j) strict-lower ; E = q_i.k_j incl-lower -> g_att
    {
        const int i0 = (tid >> 3) * 2;
        const int j0 = (tid & 7) * 4;
        float a00=0,a01=0,a02=0,a03=0,a10=0,a11=0,a12=0,a13=0;
        float e00=0,e01=0,e02=0,e03=0,e10=0,e11=0,e12=0,e13=0;
        #pragma unroll 4
        for (int d = 0; d < Dd; ++d) {
            const float* kc = skT + d*33;
            const float* qc = sqT + d*33;
            float b0=kc[j0], b1=kc[j0+1], b2=kc[j0+2], b3=kc[j0+3];
            float ka0=kc[i0], ka1=kc[i0+1], qa0=qc[i0], qa1=qc[i0+1];
            a00+=ka0*b0; a01+=ka0*b1; a02+=ka0*b2; a03+=ka0*b3;
            a10+=ka1*b0; a11+=ka1*b1; a12+=ka1*b2; a13+=ka1*b3;
            e00+=qa0*b0; e01+=qa0*b1; e02+=qa0*b2; e03+=qa0*b3;
            e10+=qa1*b0; e11+=qa1*b1; e12+=qa1*b2; e13+=qa1*b3;
        }
        float nb0 = -sbeta[i0], nb1 = -sbeta[i0+1];
        sA[(i0  )*33+j0  ] = (j0  <i0  ) ? nb0*a00 : 0.f;
        sA[(i0  )*33+j0+1] = (j0+1<i0  ) ? nb0*a01 : 0.f;
        sA[(i0  )*33+j0+2] = (j0+2<i0  ) ? nb0*a02 : 0.f;
        sA[(i0  )*33+j0+3] = (j0+3<i0  ) ? nb0*a03 : 0.f;
        sA[(i0+1)*33+j0  ] = (j0  <i0+1) ? nb1*a10 : 0.f;
        sA[(i0+1)*33+j0+1] = (j0+1<i0+1) ? nb1*a11 : 0.f;
        sA[(i0+1)*33+j0+2] = (j0+2<i0+1) ? nb1*a12 : 0.f;
        sA[(i0+1)*33+j0+3] = (j0+3<i0+1) ? nb1*a13 : 0.f;
        float* ga = g_att + (size_t)chk*1024;
        ga[(i0  )*Cc+j0  ] = (j0  <=i0  ) ? e00 : 0.f;
        ga[(i0  )*Cc+j0+1] = (j0+1<=i0  ) ? e01 : 0.f;
        ga[(i0  )*Cc+j0+2] = (j0+2<=i0  ) ? e02 : 0.f;
        ga[(i0  )*Cc+j0+3] = (j0+3<=i0  ) ? e03 : 0.f;
        ga[(i0+1)*Cc+j0  ] = (j0  <=i0+1) ? e10 : 0.f;
        ga[(i0+1)*Cc+j0+1] = (j0+1<=i0+1) ? e11 : 0.f;
        ga[(i0+1)*Cc+j0+2] = (j0+2<=i0+1) ? e12 : 0.f;
        ga[(i0+1)*Cc+j0+3] = (j0+3<=i0+1) ? e13 : 0.f;
    }
    __syncthreads();

    // forward substitution (warp 0), then += I
    if (warp == 0) {
        for (int i = 1; i < 32; ++i) {
            float rv  = sA[i*33 + lane];
            float acc = rv;
            for (int j = 0; j < i; ++j)
                acc += __shfl_sync(0xffffffffu, rv, j) * sA[j*33 + lane];
            sA[i*33 + lane] = acc;
            __syncwarp();
        }
        sA[lane*33 + lane] += 1.0f;
    }
    __syncthreads();

    // u = T(v*beta) row-major ; w^T padded [128][36]
    {
        const int d = tid;
        #pragma unroll
        for (int rb = 0; rb < 4; ++rb) {
            const int r0 = rb*8;
            float ar[8];
            #pragma unroll
            for (int rr = 0; rr < 8; ++rr) ar[rr] = sA[(r0+rr)*33 + lane];
            float au[8] = {0,0,0,0,0,0,0,0};
            float aw[8] = {0,0,0,0,0,0,0,0};
            for (int j = 0; j < 32; ++j) {
                float vb = svb[j*Dd + d];
                float kb = skT[d*33 + j] * sbeta[j];
                #pragma unroll
                for (int rr = 0; rr < 8; ++rr) {
                    float a = __shfl_sync(0xffffffffu, ar[rr], j);
                    au[rr] += a*vb;
                    aw[rr] += a*kb;
                }
            }
            #pragma unroll
            for (int rr = 0; rr < 8; ++rr)
                g_u[base + (size_t)(r0+rr)*Dd + d] = au[rr];
            *(float4*)&g_wT36[(size_t)chk*4608 + d*36 + r0    ] = make_float4(aw[0],aw[1],aw[2],aw[3]);
            *(float4*)&g_wT36[(size_t)chk*4608 + d*36 + r0 + 4] = make_float4(aw[4],aw[5],aw[6],aw[7]);
        }
    }
}

// ----------------------------------------------------------------------------
// Kernel 1b: pair matrices M = w_b @ k_a^T. grid = 1024, block = 128.
// ----------------------------------------------------------------------------
__global__ __launch_bounds__(128) void mmat_kernel()
{
    __shared__ float sw[4608];   // w^T chunk b [128][36]
    __shared__ float sk[4608];   // k^T chunk a [128][36]

    const int p  = blockIdx.x;           // pair index 0..1023
    const int bh = p >> 6;
    const int t  = p & 63;
    const int a  = bh*NCH + 2*t;
    const int b  = a + 1;
    const int tid = threadIdx.x;

    #pragma unroll
    for (int it = 0; it < 9; ++it) {
        int i4 = (tid + it*128) * 4;
        *(float4*)&sw[i4] = *(const float4*)&g_wT36[(size_t)b*4608 + i4];
        *(float4*)&sk[i4] = *(const float4*)&g_kT36[(size_t)a*4608 + i4];
    }
    __syncthreads();

    const int i0 = (tid >> 3) * 2;       // M row (w_b row)
    const int j0 = (tid & 7) * 4;        // M col (k_a row)
    float m00=0,m01=0,m02=0,m03=0,m10=0,m11=0,m12=0,m13=0;
    #pragma unroll 4
    for (int d = 0; d < 128; ++d) {
        float w0 = sw[d*36 + i0];
        float w1 = sw[d*36 + i0 + 1];
        float4 kk = *(const float4*)&sk[d*36 + j0];
        m00 += w0*kk.x; m01 += w0*kk.y; m02 += w0*kk.z; m03 += w0*kk.w;
        m10 += w1*kk.x; m11 += w1*kk.y; m12 += w1*kk.z; m13 += w1*kk.w;
    }
    float* gm = g_M + (size_t)p*1152;
    *(float4*)&gm[(i0  )*36 + j0] = make_float4(m00, m01, m02, m03);
    *(float4*)&gm[(i0+1)*36 + j0] = make_float4(m10, m11, m12, m13);
}

// ----------------------------------------------------------------------------
// Kernel 2: double-chunk scan. grid = (8,16), block = 512; 64 serial iters.
// ----------------------------------------------------------------------------
#define WST 36
#define SST 20
#define CH2_F 9216       // floats per double-chunk (w or k) buffer
#define CH2_B 36864
#define M_F 1152
#define M_B 4608
#define TX_BYTES (2*CH2_B + M_B)   // 78336

__global__ __launch_bounds__(512, 1) void scan_kernel(float* __restrict__ out)
{
    extern __shared__ float sm2[];
    float* swT = sm2;                   // [2][2 chunks][128][36]
    float* skT = swT + 2*CH2_F;         // [2][2 chunks][128][36]
    float* sM  = skT + 2*CH2_F;         // [2][32][36]
    float* sS  = sM  + 2*M_F;           // [128][20]
    float* sYp = sS  + 2560;            // [8][64][20]
    float* su2a= sYp + 10240;           // [32][20]
    float* su2b= su2a+ 640;             // [32][20]
    float* smb = su2b+ 640;             // 2 mbarriers

    const int cb = blockIdx.x;
    const int bh = blockIdx.y;
    const int colbase = cb * DVB;
    const int tid  = threadIdx.x;
    const int lane = tid & 31;
    const int warp = tid >> 5;

    const unsigned sw_u32 = smem_u32(swT);
    const unsigned sk_u32 = smem_u32(skT);
    const unsigned sm_u32 = smem_u32(sM);
    const unsigned mb_u32 = smem_u32(smb);

    // Y roles: dq = 16-d slice (0..7), rh = chunk half (0=a,1=b); lane = row
    const int dq = warp >> 1;
    const int rh = warp & 1;
    // update roles: lane owns S[sd][uc4..+3]
    const int sd  = (warp >> 2)*32 + lane;
    const int uc4 = (warp & 3) * 4;
    // u' roles: r = tid>>4, c = tid&15
    const int upr = tid >> 4;
    const int upc = tid & 15;

    u64t s01 = 0ull, s23 = 0ull;
    for (int i = tid; i < 2560; i += 512) sS[i] = 0.f;

    if (tid == 0) { mbar_init(mb_u32, 1); mbar_init(mb_u32 + 8, 1); }
    __syncthreads();
    if (tid == 0) {
        const size_t ca = (size_t)(bh*NCH);
        mbar_expect_tx(mb_u32, TX_BYTES);
        tma_bulk_g2s(sw_u32, g_wT36 + ca*4608, CH2_B, mb_u32);
        tma_bulk_g2s(sk_u32, g_kT36 + ca*4608, CH2_B, mb_u32);
        tma_bulk_g2s(sm_u32, g_M + (size_t)(bh*64)*1152, M_B, mb_u32);
    }
    float rua = g_u[((size_t)bh*Ll + upr)*Dd + colbase + upc];
    float rub = g_u[((size_t)bh*Ll + 32 + upr)*Dd + colbase + upc];

    for (int t = 0; t < 64; ++t) {
        const int buf = t & 1;
        const int chka = bh*NCH + 2*t;
        const int chkb = chka + 1;

        // TMA for t+1
        if (tid == 0 && t + 1 < 64) {
            const int b2 = (t + 1) & 1;
            mbar_expect_tx(mb_u32 + b2*8, TX_BYTES);
            tma_bulk_g2s(sw_u32 + b2*CH2_B, g_wT36 + (size_t)(chka+2)*4608, CH2_B, mb_u32 + b2*8);
            tma_bulk_g2s(sk_u32 + b2*CH2_B, g_kT36 + (size_t)(chka+2)*4608, CH2_B, mb_u32 + b2*8);
            tma_bulk_g2s(sm_u32 + b2*M_B,   g_M + (size_t)(bh*64 + t + 1)*1152, M_B, mb_u32 + b2*8);
        }
        // persist S_a (pre-chunk a), col-major [c][d]
        {
            float2 aa = up2(s01), bb = up2(s23);
            float* gs = g_S + (size_t)chka*16384 + (size_t)(colbase + uc4)*128 + sd;
            gs[0] = aa.x; gs[128] = aa.y; gs[256] = bb.x; gs[384] = bb.y;
        }
        // prefetch next u elements
        float rua_n = rua, rub_n = rub;
        if (t + 1 < 64) {
            const size_t rbase = (size_t)bh*Ll + (size_t)(2*t+2)*Cc;
            rua_n = g_u[(rbase + upr)*Dd + colbase + upc];
            rub_n = g_u[(rbase + 32 + upr)*Dd + colbase + upc];
        }

        mbar_wait(mb_u32 + buf*8, (unsigned)((t >> 1) & 1));

        // Y: [w_a; w_b](64x128) @ S(128x16); warp: d-slice dq, chunk rh, 16 cols
        {
            const float* xw = swT + buf*CH2_F + rh*4608;
            u64t y0=0ull,y1=0ull,y2=0ull,y3=0ull,y4=0ull,y5=0ull,y6=0ull,y7=0ull;
            #pragma unroll
            for (int j = 0; j < 16; ++j) {
                const int jd = dq*16 + j;
                u64t xx = pk2s(xw[jd*WST + lane]);
                ulonglong2 sa = *(const ulonglong2*)&sS[jd*SST];
                ulonglong2 sb = *(const ulonglong2*)&sS[jd*SST + 4];
                ulonglong2 sc = *(const ulonglong2*)&sS[jd*SST + 8];
                ulonglong2 sd2= *(const ulonglong2*)&sS[jd*SST + 12];
                y0 = f2(xx, sa.x, y0); y1 = f2(xx, sa.y, y1);
                y2 = f2(xx, sb.x, y2); y3 = f2(xx, sb.y, y3);
                y4 = f2(xx, sc.x, y4); y5 = f2(xx, sc.y, y5);
                y6 = f2(xx, sd2.x, y6); y7 = f2(xx, sd2.y, y7);
            }
            float* yp = sYp + dq*1280 + (rh*32 + lane)*SST;
            ulonglong2 o;
            o.x = y0; o.y = y1; *(ulonglong2*)(yp     ) = o;
            o.x = y2; o.y = y3; *(ulonglong2*)(yp + 4 ) = o;
            o.x = y4; o.y = y5; *(ulonglong2*)(yp + 8 ) = o;
            o.x = y6; o.y = y7; *(ulonglong2*)(yp + 12) = o;
        }
        __syncthreads();   // barrier 1

        // u'_a and partial u~_b (all 512 threads, one element each)
        float accb;
        {
            float acca = rua;
            accb = rub;
            #pragma unroll
            for (int d8 = 0; d8 < 8; ++d8) {
                acca -= sYp[d8*1280 + upr*SST + upc];
                accb -= sYp[d8*1280 + (32 + upr)*SST + upc];
            }
            su2a[upr*SST + upc] = acca;
            g_u2[(size_t)chka*4096 + upr*128 + colbase + upc] = acca;
        }
        __syncthreads();   // barrier 2

        // update1: S += k_a^T @ su2a
        {
            const float* kp = skT + buf*CH2_F + sd*WST;
            #pragma unroll
            for (int r4 = 0; r4 < 8; ++r4) {
                float4 k4 = *(const float4*)(kp + r4*4);
                ulonglong2 u0 = *(const ulonglong2*)&su2a[(r4*4    )*SST + uc4];
                ulonglong2 u1 = *(const ulonglong2*)&su2a[(r4*4 + 1)*SST + uc4];
                ulonglong2 u2 = *(const ulonglong2*)&su2a[(r4*4 + 2)*SST + uc4];
                ulonglong2 u3 = *(const ulonglong2*)&su2a[(r4*4 + 3)*SST + uc4];
                u64t kk;
                kk = pk2s(k4.x); s01 = f2(kk, u0.x, s01); s23 = f2(kk, u0.y, s23);
                kk = pk2s(k4.y); s01 = f2(kk, u1.x, s01); s23 = f2(kk, u1.y, s23);
                kk = pk2s(k4.z); s01 = f2(kk, u2.x, s01); s23 = f2(kk, u2.y, s23);
                kk = pk2s(k4.w); s01 = f2(kk, u3.x, s01); s23 = f2(kk, u3.y, s23);
            }
        }
        // persist S_b (= S_a + k_a^T u'_a), col-major
        {
            float2 aa = up2(s01), bb = up2(s23);
            float* gs = g_S + (size_t)chkb*16384 + (size_t)(colbase + uc4)*128 + sd;
            gs[0] = aa.x; gs[128] = aa.y; gs[256] = bb.x; gs[384] = bb.y;
        }
        // u'_b = u~_b - M @ u'_a
        {
            const float* Mp = sM + buf*M_F + upr*36;
            #pragma unroll 8
            for (int j = 0; j < 32; ++j)
                accb -= Mp[j] * su2a[j*SST + upc];
            su2b[upr*SST + upc] = accb;
            g_u2[(size_t)chkb*4096 + upr*128 + colbase + upc] = accb;
        }
        __syncthreads();   // barrier 3

        // update2: S += k_b^T @ su2b ; publish sS for next Y
        {
            const float* kp = skT + buf*CH2_F + 4608 + sd*WST;
            #pragma unroll
            for (int r4 = 0; r4 < 8; ++r4) {
                float4 k4 = *(const float4*)(kp + r4*4);
                ulonglong2 u0 = *(const ulonglong2*)&su2b[(r4*4    )*SST + uc4];
                ulonglong2 u1 = *(const ulonglong2*)&su2b[(r4*4 + 1)*SST + uc4];
                ulonglong2 u2 = *(const ulonglong2*)&su2b[(r4*4 + 2)*SST + uc4];
                ulonglong2 u3 = *(const ulonglong2*)&su2b[(r4*4 + 3)*SST + uc4];
                u64t kk;
                kk = pk2s(k4.x); s01 = f2(kk, u0.x, s01); s23 = f2(kk, u0.y, s23);
                kk = pk2s(k4.y); s01 = f2(kk, u1.x, s01); s23 = f2(kk, u1.y, s23);
                kk = pk2s(k4.z); s01 = f2(kk, u2.x, s01); s23 = f2(kk, u2.y, s23);
                kk = pk2s(k4.w); s01 = f2(kk, u3.x, s01); s23 = f2(kk, u3.y, s23);
            }
            ulonglong2 sv; sv.x = s01; sv.y = s23;
            *(ulonglong2*)&sS[sd*SST + uc4] = sv;
        }
        rua = rua_n; rub = rub_n;
        __syncthreads();   // barrier 4
    }

    // final S -> out
    {
        float2 aa = up2(s01), bb = up2(s23);
        *(float4*)&out[O_ELEMS + ((size_t)bh*Dd + sd)*Dd + colbase + uc4] =
            make_float4(aa.x, aa.y, bb.x, bb.y);
    }
}

// ----------------------------------------------------------------------------
// Kernel 3: epilogue o = q@S_i + A@u'_i. grid = (NCH, BHh), block = 256.
// ----------------------------------------------------------------------------
#define AST 36

__global__ __launch_bounds__(256) void epi_kernel(float* __restrict__ out)
{
    extern __shared__ float sm3[];
    float* sS = sm3;              // [128][132]
    float* sq = sS + 128*132;     // [32][132]
    float* su = sq + 32*132;      // [32][132]
    float* sA = su + 32*132;      // [32][36]

    const int ci = blockIdx.x;
    const int bh = blockIdx.y;
    const int chk = bh*NCH + ci;
    const int tid = threadIdx.x;
    const size_t qbase = ((size_t)bh*Ll + (size_t)ci*Cc)*Dd;

    {
        const int c = tid >> 1;
        const int db = (tid & 1) * 64;
        const float* gs = g_S + (size_t)chk*16384 + (size_t)c*128 + db;
        #pragma unroll
        for (int i = 0; i < 16; ++i) {
            float4 f = *(const float4*)(gs + i*4);
            int d = db + i*4;
            sS[(d  )*132 + c] = f.x; sS[(d+1)*132 + c] = f.y;
            sS[(d+2)*132 + c] = f.z; sS[(d+3)*132 + c] = f.w;
        }
    }
    {
        #pragma unroll
        for (int t = 0; t < 4; ++t) {
            int i4 = (tid + t*256) * 4;
            float4 f = *(const float4*)(g_qn + qbase + i4);
            *(float4*)&sq[(i4 >> 7)*132 + (i4 & 127)] = f;
        }
    }
    {
        #pragma unroll
        for (int t = 0; t < 4; ++t) {
            int i4 = (tid + t*256) * 4;
            float4 f = *(const float4*)(g_u2 + (size_t)chk*4096 + i4);
            *(float4*)&su[(i4 >> 7)*132 + (i4 & 127)] = f;
        }
    }
    {
        int i4 = tid * 4;
        float4 f = *(const float4*)(g_att + (size_t)chk*1024 + i4);
        *(float4*)&sA[(i4 >> 5)*AST + (i4 & 31)] = f;
    }
    __syncthreads();

    const int m0 = (tid >> 4) * 2;
    const int m1 = m0 + 1;
    const int cbk = (tid & 15) * 8;
    float4 a00 = make_float4(0,0,0,0), a01 = a00, a10 = a00, a11 = a00;
    #pragma unroll 8
    for (int d = 0; d < 128; ++d) {
        float q0 = sq[m0*132 + d];
        float q1 = sq[m1*132 + d];
        float4 s0 = *(const float4*)&sS[d*132 + cbk];
        float4 s1 = *(const float4*)&sS[d*132 + cbk + 4];
        a00.x += q0*s0.x; a00.y += q0*s0.y; a00.z += q0*s0.z; a00.w += q0*s0.w;
        a01.x += q0*s1.x; a01.y += q0*s1.y; a01.z += q0*s1.z; a01.w += q0*s1.w;
        a10.x += q1*s0.x; a10.y += q1*s0.y; a10.z += q1*s0.z; a10.w += q1*s0.w;
        a11.x += q1*s1.x; a11.y += q1*s1.y; a11.z += q1*s1.z; a11.w += q1*s1.w;
    }
    #pragma unroll 8
    for (int j = 0; j < 32; ++j) {
        float p0 = sA[m0*AST + j];
        float p1 = sA[m1*AST + j];
        float4 u0 = *(const float4*)&su[j*132 + cbk];
        float4 u1 = *(const float4*)&su[j*132 + cbk + 4];
        a00.x += p0*u0.x; a00.y += p0*u0.y; a00.z += p0*u0.z; a00.w += p0*u0.w;
        a01.x += p0*u1.x; a01.y += p0*u1.y; a01.z += p0*u1.z; a01.w += p0*u1.w;
        a10.x += p1*u0.x; a10.y += p1*u0.y; a10.z += p1*u0.z; a10.w += p1*u0.w;
        a11.x += p1*u1.x; a11.y += p1*u1.y; a11.z += p1*u1.z; a11.w += p1*u1.w;
    }
    float* o0 = out + qbase + (size_t)m0*Dd + cbk;
    float* o1 = out + qbase + (size_t)m1*Dd + cbk;
    *(float4*)(o0)     = a00; *(float4*)(o0 + 4) = a01;
    *(float4*)(o1)     = a10; *(float4*)(o1 + 4) = a11;
}

// ----------------------------------------------------------------------------
extern "C" void kernel_launch(void* const* d_in, const int* in_sizes, int n_in,
                              void* d_out, int out_size)
{
    const float* q    = (const float*)d_in[0];
    const float* k    = (const float*)d_in[1];
    const float* v    = (const float*)d_in[2];
    const float* beta = (const float*)d_in[3];
    float* out = (float*)d_out;

    const int smem1 = (2*4224 + 4096 + 1056 + 32) * 4;                      // 54528
    const int smem2 = (4*CH2_F + 2*M_F + 2560 + 10240 + 640 + 640 + 8) * 4; // 213024
    const int smem3 = (128*132 + 32*132 + 32*132 + 32*AST) * 4;             // 105984
    cudaFuncSetAttribute(prep_kernel, cudaFuncAttributeMaxDynamicSharedMemorySize, smem1);
    cudaFuncSetAttribute(scan_kernel, cudaFuncAttributeMaxDynamicSharedMemorySize, smem2);
    cudaFuncSetAttribute(epi_kernel,  cudaFuncAttributeMaxDynamicSharedMemorySize, smem3);

    prep_kernel<<<NCHK, 128, smem1>>>(q, k, v, beta);
    mmat_kernel<<<NPAIR, 128>>>();
    scan_kernel<<<dim3(NDVB, BHh), 512, smem2>>>(out);
    epi_kernel<<<dim3(NCH, BHh), 256, smem3>>>(out);
}

// round 17
// speedup vs baseline: 1.1344x; 1.1344x over previous
#include <cuda_runtime.h>

#define Ll 4096
#define Dd 128
#define Cc 32
#define NCH 128
#define BHh 16
#define DVB 16
#define NDVB 8
#define ELEMS (BHh*Ll*Dd)
#define O_ELEMS ((size_t)ELEMS)
#define NCHK (BHh*NCH)

typedef unsigned long long u64t;
__device__ __forceinline__ u64t pk2s(float a){
    u64t r; asm("mov.b64 %0,{%1,%1};" : "=l"(r) : "f"(a)); return r;
}
__device__ __forceinline__ u64t f2(u64t a, u64t b, u64t c){
    u64t d; asm("fma.rn.f32x2 %0,%1,%2,%3;" : "=l"(d) : "l"(a), "l"(b), "l"(c)); return d;
}
__device__ __forceinline__ float2 up2(u64t p){
    float lo, hi; asm("mov.b64 {%0,%1},%2;" : "=f"(lo), "=f"(hi) : "l"(p));
    return make_float2(lo, hi);
}

// Scratch (__device__ globals)
__device__ float g_qn  [ELEMS];               // q normalized (epilogue)
__device__ float g_u   [ELEMS];               // u = T(v*beta) row-major (scan)
__device__ float g_wT36[NCHK*4608];           // per chunk: w^T [128][36] padded
__device__ float g_kT36[NCHK*4608];           // per chunk: k^T [128][36] padded
__device__ float g_att [NCHK*1024];           // attn_local (epilogue)
__device__ float g_S   [(size_t)NCHK*16384];  // per chunk: S_i col-major [c][d]
__device__ float g_u2  [NCHK*4096];           // per chunk: u' ROW-major [r][c]

__device__ __forceinline__ unsigned smem_u32(const void* p){
    unsigned a;
    asm("{ .reg .u64 t; cvta.to.shared.u64 t, %1; cvt.u32.u64 %0, t; }"
        : "=r"(a) : "l"(p));
    return a;
}
__device__ __forceinline__ void mbar_init(unsigned mbar, unsigned cnt){
    asm volatile("mbarrier.init.shared.b64 [%0], %1;" :: "r"(mbar), "r"(cnt) : "memory");
}
__device__ __forceinline__ void mbar_expect_tx(unsigned mbar, unsigned bytes){
    asm volatile("mbarrier.arrive.expect_tx.shared.b64 _, [%0], %1;"
                 :: "r"(mbar), "r"(bytes) : "memory");
}
__device__ __forceinline__ void tma_bulk_g2s(unsigned dst, const void* src,
                                             unsigned bytes, unsigned mbar){
    asm volatile("cp.async.bulk.shared::cta.global.mbarrier::complete_tx::bytes "
                 "[%0], [%1], %2, [%3];"
                 :: "r"(dst), "l"(src), "r"(bytes), "r"(mbar) : "memory");
}
__device__ __forceinline__ void mbar_wait(unsigned mbar, unsigned parity){
    asm volatile("{\n\t.reg .pred P;\n"
                 "WAIT_%=:\n\t"
                 "mbarrier.try_wait.parity.acquire.cta.shared::cta.b64 P, [%0], %1;\n\t"
                 "@!P bra WAIT_%=;\n\t}"
                 :: "r"(mbar), "r"(parity) : "memory");
}

// ----------------------------------------------------------------------------
// Kernel 1: per-chunk preprocessing. grid = 2048, block = 128 (612us winner)
// ----------------------------------------------------------------------------
__global__ __launch_bounds__(128) void prep_kernel(
    const float* __restrict__ q, const float* __restrict__ k,
    const float* __restrict__ v, const float* __restrict__ beta)
{
    extern __shared__ float sm1[];
    float* sqT   = sm1;                // [128][33]
    float* skT   = sqT + 4224;         // [128][33]
    float* svb   = skT + 4224;         // [32][128]
    float* sA    = svb + 4096;         // [32][33]
    float* sbeta = sA  + 1056;         // [32]

    const int tid  = threadIdx.x;
    const int lane = tid & 31;
    const int warp = tid >> 5;
    const int bh = blockIdx.x >> 7;
    const int ci = blockIdx.x & 127;
    const int chk = blockIdx.x;
    const size_t base = ((size_t)bh*Ll + (size_t)ci*Cc)*Dd;

    for (int r = warp*8; r < warp*8 + 8; ++r) {
        float bet = beta[(size_t)bh*Ll + ci*Cc + r];
        const float4 xq = *(const float4*)(q + base + r*Dd + lane*4);
        const float4 xk = *(const float4*)(k + base + r*Dd + lane*4);
        const float4 xv = *(const float4*)(v + base + r*Dd + lane*4);
        float s2q = xq.x*xq.x + xq.y*xq.y + xq.z*xq.z + xq.w*xq.w;
        float s2k = xk.x*xk.x + xk.y*xk.y + xk.z*xk.z + xk.w*xk.w;
        #pragma unroll
        for (int o = 16; o; o >>= 1) {
            s2q += __shfl_xor_sync(0xffffffffu, s2q, o);
            s2k += __shfl_xor_sync(0xffffffffu, s2k, o);
        }
        float iq = rsqrtf(s2q + 1e-6f);
        float ik = rsqrtf(s2k + 1e-6f);
        float4 nq = make_float4(xq.x*iq, xq.y*iq, xq.z*iq, xq.w*iq);
        float4 nk = make_float4(xk.x*ik, xk.y*ik, xk.z*ik, xk.w*ik);
        *(float4*)(g_qn + base + r*Dd + lane*4) = nq;
        const int d0 = lane*4;
        sqT[(d0+0)*33 + r] = nq.x; sqT[(d0+1)*33 + r] = nq.y;
        sqT[(d0+2)*33 + r] = nq.z; sqT[(d0+3)*33 + r] = nq.w;
        skT[(d0+0)*33 + r] = nk.x; skT[(d0+1)*33 + r] = nk.y;
        skT[(d0+2)*33 + r] = nk.z; skT[(d0+3)*33 + r] = nk.w;
        *(float4*)(svb + r*Dd + d0) = make_float4(xv.x*bet, xv.y*bet, xv.z*bet, xv.w*bet);
        if (lane == 0) sbeta[r] = bet;
    }
    __syncthreads();

    // k^T padded [128][36] (TMA target layout)
    {
        const int d = tid;
        #pragma unroll
        for (int r4 = 0; r4 < 32; r4 += 4) {
            *(float4*)&g_kT36[(size_t)chk*4608 + d*36 + r4] = make_float4(
                skT[d*33+r4], skT[d*33+r4+1], skT[d*33+r4+2], skT[d*33+r4+3]);
        }
    }

    // A = -beta_i (k_i.k_j) strict-lower ; E = q_i.k_j incl-lower -> g_att
    {
        const int i0 = (tid >> 3) * 2;
        const int j0 = (tid & 7) * 4;
        float a00=0,a01=0,a02=0,a03=0,a10=0,a11=0,a12=0,a13=0;
        float e00=0,e01=0,e02=0,e03=0,e10=0,e11=0,e12=0,e13=0;
        #pragma unroll 4
        for (int d = 0; d < Dd; ++d) {
            const float* kc = skT + d*33;
            const float* qc = sqT + d*33;
            float b0=kc[j0], b1=kc[j0+1], b2=kc[j0+2], b3=kc[j0+3];
            float ka0=kc[i0], ka1=kc[i0+1], qa0=qc[i0], qa1=qc[i0+1];
            a00+=ka0*b0; a01+=ka0*b1; a02+=ka0*b2; a03+=ka0*b3;
            a10+=ka1*b0; a11+=ka1*b1; a12+=ka1*b2; a13+=ka1*b3;
            e00+=qa0*b0; e01+=qa0*b1; e02+=qa0*b2; e03+=qa0*b3;
            e10+=qa1*b0; e11+=qa1*b1; e12+=qa1*b2; e13+=qa1*b3;
        }
        float nb0 = -sbeta[i0], nb1 = -sbeta[i0+1];
        sA[(i0  )*33+j0  ] = (j0  <i0  ) ? nb0*a00 : 0.f;
        sA[(i0  )*33+j0+1] = (j0+1<i0  ) ? nb0*a01 : 0.f;
        sA[(i0  )*33+j0+2] = (j0+2<i0  ) ? nb0*a02 : 0.f;
        sA[(i0  )*33+j0+3] = (j0+3<i0  ) ? nb0*a03 : 0.f;
        sA[(i0+1)*33+j0  ] = (j0  <i0+1) ? nb1*a10 : 0.f;
        sA[(i0+1)*33+j0+1] = (j0+1<i0+1) ? nb1*a11 : 0.f;
        sA[(i0+1)*33+j0+2] = (j0+2<i0+1) ? nb1*a12 : 0.f;
        sA[(i0+1)*33+j0+3] = (j0+3<i0+1) ? nb1*a13 : 0.f;
        float* ga = g_att + (size_t)chk*1024;
        ga[(i0  )*Cc+j0  ] = (j0  <=i0  ) ? e00 : 0.f;
        ga[(i0  )*Cc+j0+1] = (j0+1<=i0  ) ? e01 : 0.f;
        ga[(i0  )*Cc+j0+2] = (j0+2<=i0  ) ? e02 : 0.f;
        ga[(i0  )*Cc+j0+3] = (j0+3<=i0  ) ? e03 : 0.f;
        ga[(i0+1)*Cc+j0  ] = (j0  <=i0+1) ? e10 : 0.f;
        ga[(i0+1)*Cc+j0+1] = (j0+1<=i0+1) ? e11 : 0.f;
        ga[(i0+1)*Cc+j0+2] = (j0+2<=i0+1) ? e12 : 0.f;
        ga[(i0+1)*Cc+j0+3] = (j0+3<=i0+1) ? e13 : 0.f;
    }
    __syncthreads();

    // forward substitution (warp 0), then += I
    if (warp == 0) {
        for (int i = 1; i < 32; ++i) {
            float rv  = sA[i*33 + lane];
            float acc = rv;
            for (int j = 0; j < i; ++j)
                acc += __shfl_sync(0xffffffffu, rv, j) * sA[j*33 + lane];
            sA[i*33 + lane] = acc;
            __syncwarp();
        }
        sA[lane*33 + lane] += 1.0f;
    }
    __syncthreads();

    // u = T(v*beta) row-major ; w^T padded [128][36]
    {
        const int d = tid;
        #pragma unroll
        for (int rb = 0; rb < 4; ++rb) {
            const int r0 = rb*8;
            float ar[8];
            #pragma unroll
            for (int rr = 0; rr < 8; ++rr) ar[rr] = sA[(r0+rr)*33 + lane];
            float au[8] = {0,0,0,0,0,0,0,0};
            float aw[8] = {0,0,0,0,0,0,0,0};
            for (int j = 0; j < 32; ++j) {
                float vb = svb[j*Dd + d];
                float kb = skT[d*33 + j] * sbeta[j];
                #pragma unroll
                for (int rr = 0; rr < 8; ++rr) {
                    float a = __shfl_sync(0xffffffffu, ar[rr], j);
                    au[rr] += a*vb;
                    aw[rr] += a*kb;
                }
            }
            #pragma unroll
            for (int rr = 0; rr < 8; ++rr)
                g_u[base + (size_t)(r0+rr)*Dd + d] = au[rr];
            *(float4*)&g_wT36[(size_t)chk*4608 + d*36 + r0    ] = make_float4(aw[0],aw[1],aw[2],aw[3]);
            *(float4*)&g_wT36[(size_t)chk*4608 + d*36 + r0 + 4] = make_float4(aw[4],aw[5],aw[6],aw[7]);
        }
    }
}

// ----------------------------------------------------------------------------
// Kernel 2: sequential scan. grid = (8,16), block = 512. (612us winner)
// ----------------------------------------------------------------------------
#define WST 36
#define SST 20
#define TILE_F 4608
#define TILE_B 18432

__global__ __launch_bounds__(512, 1) void scan_kernel(float* __restrict__ out)
{
    extern __shared__ float sm2[];
    float* swT = sm2;                   // [2][128][36] w^T
    float* skT = swT + 2*TILE_F;        // [2][128][36] k^T
    float* sS  = skT + 2*TILE_F;        // [128][20]
    float* sYp = sS  + 2560;            // [8][32][20]
    float* su2 = sYp + 5120;            // [32][20]
    float* smb = su2 + 640;             // mbarriers (2 x 8B)

    const int cb = blockIdx.x;
    const int bh = blockIdx.y;
    const int colbase = cb * DVB;
    const int tid  = threadIdx.x;
    const int lane = tid & 31;
    const int warp = tid >> 5;

    const unsigned sw_u32 = smem_u32(swT);
    const unsigned sk_u32 = smem_u32(skT);
    const unsigned mb_u32 = smem_u32(smb);

    const int dq  = warp >> 1;
    const int cg8 = (warp & 1) * 8;
    const int sd  = (warp >> 2)*32 + lane;
    const int uc4 = (warp & 3) * 4;
    const int upr = tid >> 4;
    const int upc = tid & 15;

    u64t s01 = 0ull, s23 = 0ull;
    for (int i = tid; i < 2560; i += 512) sS[i] = 0.f;

    if (tid == 0) { mbar_init(mb_u32, 1); mbar_init(mb_u32 + 8, 1); }
    __syncthreads();
    if (tid == 0) {
        const size_t tb = (size_t)(bh*NCH)*TILE_F;
        mbar_expect_tx(mb_u32, 2*TILE_B);
        tma_bulk_g2s(sw_u32, g_wT36 + tb, TILE_B, mb_u32);
        tma_bulk_g2s(sk_u32, g_kT36 + tb, TILE_B, mb_u32);
    }
    float ruu = g_u[((size_t)bh*Ll + upr)*Dd + colbase + upc];

    for (int ci = 0; ci < NCH; ++ci) {
        const int buf = ci & 1;
        const int chk = bh*NCH + ci;

        if (tid == 0 && ci + 1 < NCH) {
            const int b2 = (ci + 1) & 1;
            const size_t tb = (size_t)(chk + 1)*TILE_F;
            mbar_expect_tx(mb_u32 + b2*8, 2*TILE_B);
            tma_bulk_g2s(sw_u32 + b2*TILE_B, g_wT36 + tb, TILE_B, mb_u32 + b2*8);
            tma_bulk_g2s(sk_u32 + b2*TILE_B, g_kT36 + tb, TILE_B, mb_u32 + b2*8);
        }
        float ru_next = ruu;
        if (ci + 1 < NCH)
            ru_next = g_u[((size_t)bh*Ll + (size_t)(ci+1)*Cc + upr)*Dd + colbase + upc];

        mbar_wait(mb_u32 + buf*8, (unsigned)((ci >> 1) & 1));

        // persist S_i (pre-chunk), col-major [c][d]
        {
            float2 a = up2(s01), b = up2(s23);
            float* gs = g_S + (size_t)chk*16384 + (size_t)(colbase + uc4)*128 + sd;
            gs[0] = a.x; gs[128] = a.y; gs[256] = b.x; gs[384] = b.y;
        }

        // Y: partial of w(32x128)@S(128x16)
        {
            const float* xw = swT + buf*TILE_F;
            u64t y0=0ull, y1=0ull, y2=0ull, y3=0ull;
            #pragma unroll
            for (int j = 0; j < 16; ++j) {
                const int jd = dq*16 + j;
                u64t xx = pk2s(xw[jd*WST + lane]);
                ulonglong2 sa = *(const ulonglong2*)&sS[jd*SST + cg8];
                ulonglong2 sb = *(const ulonglong2*)&sS[jd*SST + cg8 + 4];
                y0 = f2(xx, sa.x, y0); y1 = f2(xx, sa.y, y1);
                y2 = f2(xx, sb.x, y2); y3 = f2(xx, sb.y, y3);
            }
            ulonglong2 o1; o1.x = y0; o1.y = y1;
            ulonglong2 o2; o2.x = y2; o2.y = y3;
            *(ulonglong2*)&sYp[dq*640 + lane*SST + cg8    ] = o1;
            *(ulonglong2*)&sYp[dq*640 + lane*SST + cg8 + 4] = o2;
        }
        __syncthreads();

        // u' = u - w@S
        {
            float acc = ruu;
            #pragma unroll
            for (int d8 = 0; d8 < 8; ++d8)
                acc -= sYp[d8*640 + upr*SST + upc];
            su2[upr*SST + upc] = acc;
            g_u2[(size_t)chk*4096 + upr*128 + colbase + upc] = acc;
        }
        __syncthreads();

        // S += k^T @ u'
        {
            const float* kp = skT + buf*TILE_F + sd*WST;
            #pragma unroll
            for (int r4 = 0; r4 < 8; ++r4) {
                float4 k4 = *(const float4*)(kp + r4*4);
                ulonglong2 u0 = *(const ulonglong2*)&su2[(r4*4    )*SST + uc4];
                ulonglong2 u1 = *(const ulonglong2*)&su2[(r4*4 + 1)*SST + uc4];
                ulonglong2 u2 = *(const ulonglong2*)&su2[(r4*4 + 2)*SST + uc4];
                ulonglong2 u3 = *(const ulonglong2*)&su2[(r4*4 + 3)*SST + uc4];
                u64t kk;
                kk = pk2s(k4.x); s01 = f2(kk, u0.x, s01); s23 = f2(kk, u0.y, s23);
                kk = pk2s(k4.y); s01 = f2(kk, u1.x, s01); s23 = f2(kk, u1.y, s23);
                kk = pk2s(k4.z); s01 = f2(kk, u2.x, s01); s23 = f2(kk, u2.y, s23);
                kk = pk2s(k4.w); s01 = f2(kk, u3.x, s01); s23 = f2(kk, u3.y, s23);
            }
            ulonglong2 sv; sv.x = s01; sv.y = s23;
            *(ulonglong2*)&sS[sd*SST + uc4] = sv;
        }
        ruu = ru_next;
        __syncthreads();
    }

    {
        float2 a = up2(s01), b = up2(s23);
        *(float4*)&out[O_ELEMS + ((size_t)bh*Dd + sd)*Dd + colbase + uc4] =
            make_float4(a.x, a.y, b.x, b.y);
    }
}

// ----------------------------------------------------------------------------
// Kernel 3: epilogue o = q@S_i + A@u'_i. grid = (NCH, BHh), block = 256.
// Warp w -> 16 cols, lane -> m row. S/u' rows read as warp-broadcast vectors.
// ----------------------------------------------------------------------------
__global__ __launch_bounds__(256) void epi_kernel(float* __restrict__ out)
{
    extern __shared__ float sm3[];
    float* sS  = sm3;              // [128][132] S row-major
    float* sqT = sS + 128*132;     // [128][33]  q^T
    float* su  = sqT + 128*33;     // [32][132]  u' rows
    float* sAT = su + 32*132;      // [32][33]   A^T

    const int ci = blockIdx.x;
    const int bh = blockIdx.y;
    const int chk = bh*NCH + ci;
    const int tid = threadIdx.x;
    const int lane = tid & 31;
    const int warp = tid >> 5;
    const size_t qbase = ((size_t)bh*Ll + (size_t)ci*Cc)*Dd;

    // stage S (col-major gmem -> row-major smem)
    {
        const int c = tid >> 1;
        const int db = (tid & 1) * 64;
        const float* gs = g_S + (size_t)chk*16384 + (size_t)c*128 + db;
        #pragma unroll
        for (int i = 0; i < 16; ++i) {
            float4 f = *(const float4*)(gs + i*4);
            int d = db + i*4;
            sS[(d  )*132 + c] = f.x; sS[(d+1)*132 + c] = f.y;
            sS[(d+2)*132 + c] = f.z; sS[(d+3)*132 + c] = f.w;
        }
    }
    // stage q transposed [d][m]
    {
        #pragma unroll
        for (int t = 0; t < 4; ++t) {
            int i4 = (tid + t*256) * 4;
            float4 f = *(const float4*)(g_qn + qbase + i4);
            int m = i4 >> 7, d = i4 & 127;
            sqT[(d  )*33 + m] = f.x; sqT[(d+1)*33 + m] = f.y;
            sqT[(d+2)*33 + m] = f.z; sqT[(d+3)*33 + m] = f.w;
        }
    }
    // stage u' rows (straight copy; g_u2 is row-major)
    {
        #pragma unroll
        for (int t = 0; t < 4; ++t) {
            int i4 = (tid + t*256) * 4;
            float4 f = *(const float4*)(g_u2 + (size_t)chk*4096 + i4);
            *(float4*)&su[(i4 >> 7)*132 + (i4 & 127)] = f;
        }
    }
    // stage A transposed [j][m]
    {
        int i4 = tid * 4;
        float4 f = *(const float4*)(g_att + (size_t)chk*1024 + i4);
        int m = i4 >> 5, j = i4 & 31;
        sAT[(j  )*33 + m] = f.x; sAT[(j+1)*33 + m] = f.y;
        sAT[(j+2)*33 + m] = f.z; sAT[(j+3)*33 + m] = f.w;
    }
    __syncthreads();

    // compute: lane = m row, warp = 16-col group; packed accumulators
    const int c0 = warp * 16;
    u64t a0=0ull,a1=0ull,a2=0ull,a3=0ull,a4=0ull,a5=0ull,a6=0ull,a7=0ull;
    #pragma unroll 4
    for (int d = 0; d < 128; ++d) {
        u64t qq = pk2s(sqT[d*33 + lane]);
        ulonglong2 s0 = *(const ulonglong2*)&sS[d*132 + c0];
        ulonglong2 s1 = *(const ulonglong2*)&sS[d*132 + c0 + 4];
        ulonglong2 s2 = *(const ulonglong2*)&sS[d*132 + c0 + 8];
        ulonglong2 s3 = *(const ulonglong2*)&sS[d*132 + c0 + 12];
        a0 = f2(qq, s0.x, a0); a1 = f2(qq, s0.y, a1);
        a2 = f2(qq, s1.x, a2); a3 = f2(qq, s1.y, a3);
        a4 = f2(qq, s2.x, a4); a5 = f2(qq, s2.y, a5);
        a6 = f2(qq, s3.x, a6); a7 = f2(qq, s3.y, a7);
    }
    #pragma unroll 4
    for (int j = 0; j < 32; ++j) {
        u64t pp = pk2s(sAT[j*33 + lane]);
        ulonglong2 u0 = *(const ulonglong2*)&su[j*132 + c0];
        ulonglong2 u1 = *(const ulonglong2*)&su[j*132 + c0 + 4];
        ulonglong2 u2 = *(const ulonglong2*)&su[j*132 + c0 + 8];
        ulonglong2 u3 = *(const ulonglong2*)&su[j*132 + c0 + 12];
        a0 = f2(pp, u0.x, a0); a1 = f2(pp, u0.y, a1);
        a2 = f2(pp, u1.x, a2); a3 = f2(pp, u1.y, a3);
        a4 = f2(pp, u2.x, a4); a5 = f2(pp, u2.y, a5);
        a6 = f2(pp, u3.x, a6); a7 = f2(pp, u3.y, a7);
    }
    float* o = out + qbase + (size_t)lane*Dd + c0;
    float2 t0, t1;
    t0 = up2(a0); t1 = up2(a1); *(float4*)(o     ) = make_float4(t0.x, t0.y, t1.x, t1.y);
    t0 = up2(a2); t1 = up2(a3); *(float4*)(o + 4 ) = make_float4(t0.x, t0.y, t1.x, t1.y);
    t0 = up2(a4); t1 = up2(a5); *(float4*)(o + 8 ) = make_float4(t0.x, t0.y, t1.x, t1.y);
    t0 = up2(a6); t1 = up2(a7); *(float4*)(o + 12) = make_float4(t0.x, t0.y, t1.x, t1.y);
}

// ----------------------------------------------------------------------------
extern "C" void kernel_launch(void* const* d_in, const int* in_sizes, int n_in,
                              void* d_out, int out_size)
{
    const float* q    = (const float*)d_in[0];
    const float* k    = (const float*)d_in[1];
    const float* v    = (const float*)d_in[2];
    const float* beta = (const float*)d_in[3];
    float* out = (float*)d_out;

    const int smem1 = (2*4224 + 4096 + 1056 + 32) * 4;                 // 54528
    const int smem2 = (4*TILE_F + 2560 + 5120 + 640 + 8) * 4;          // 107040
    const int smem3 = (128*132 + 128*33 + 32*132 + 32*33) * 4;         // 105600
    cudaFuncSetAttribute(prep_kernel, cudaFuncAttributeMaxDynamicSharedMemorySize, smem1);
    cudaFuncSetAttribute(scan_kernel, cudaFuncAttributeMaxDynamicSharedMemorySize, smem2);
    cudaFuncSetAttribute(epi_kernel,  cudaFuncAttributeMaxDynamicSharedMemorySize, smem3);

    prep_kernel<<<NCHK, 128, smem1>>>(q, k, v, beta);
    scan_kernel<<<dim3(NDVB, BHh), 512, smem2>>>(out);
    epi_kernel<<<dim3(NCH, BHh), 256, smem3>>>(out);
}